// round 4
// baseline (speedup 1.0000x reference)
#include <cuda_runtime.h>
#include <math.h>

typedef unsigned long long ull;

// Problem constants
#define Bq 4
#define Tt 256
#define Dd 256
#define D2 512
#define BT 1024
#define SCALEF 0.0625f
#define BK 16

// ---------------- scratch (static device globals; no allocation) -------------
__device__ float g_xnorm[BT * Dd];
__device__ float g_xleft[BT * D2];
__device__ float g_xright[BT * D2];
__device__ float g_xtrans[BT * D2];
__device__ float g_o[BT * D2];
__device__ float g_q[BT * D2];
__device__ float g_k[BT * D2];
__device__ float g_v[BT * D2];
__device__ float g_hseq[BT * D2];
__device__ float g_h[BT * D2];
__device__ float g_convwt[4 * D2 * D2];
__device__ float g_convp[4 * BT * D2];   // split-K conv partials
__device__ float g_A[Bq * Tt * Tt];
__device__ float g_ib[BT];
__device__ float g_fb[BT];
__device__ float g_alpha[BT];
__device__ float g_beta[BT];
__device__ float g_rowsum[BT];
__device__ float g_gnmu[16];
__device__ float g_gnrs[16];

__device__ __forceinline__ float sigm(float x) { return 1.f / (1.f + __expf(-x)); }

// ---------------- packed f32x2 helpers ----------------
__device__ __forceinline__ ull packf2(float lo, float hi) {
    ull r; asm("mov.b64 %0, {%1, %2};" : "=l"(r) : "f"(lo), "f"(hi)); return r;
}
__device__ __forceinline__ void fma2(ull& d, ull a, ull b) {
    asm("fma.rn.f32x2 %0, %1, %2, %0;" : "+l"(d) : "l"(a), "l"(b));
}
__device__ __forceinline__ float2 unpackf2(ull v) {
    float2 f; asm("mov.b64 {%0, %1}, %2;" : "=f"(f.x), "=f"(f.y) : "l"(v)); return f;
}

// ---------------- row-pair packed MMA core ----------------
// As[kk][row] layout: consecutive rows adjacent => one LDS.64/128 yields packed
// f32x2 row-pairs directly. acc[p][j]: rows (ty*2P+2p, +1) x col (tx*CN+j).
template <int BMt, int BNt>
__device__ __forceinline__ void mma_t(const float (*As)[BMt + 4], const float (*Bs)[BNt + 4],
                                      int ty, int tx, ull acc[BMt / 32][BNt / 16]) {
    constexpr int PAIRS = BMt / 32, CN = BNt / 16;
#pragma unroll
    for (int kk = 0; kk < BK; kk++) {
        ull ap[PAIRS];
        if constexpr (PAIRS == 2) {
            ulonglong2 av = *(const ulonglong2*)&As[kk][ty * 4];
            ap[0] = av.x; ap[1] = av.y;
        } else {
            ap[0] = *(const ull*)&As[kk][ty * 2];
        }
        float bv[CN];
        if constexpr (CN == 4) {
            float4 b4 = *(const float4*)&Bs[kk][tx * 4];
            bv[0] = b4.x; bv[1] = b4.y; bv[2] = b4.z; bv[3] = b4.w;
        } else {
            float2 b2 = *(const float2*)&Bs[kk][tx * 2];
            bv[0] = b2.x; bv[1] = b2.y;
        }
#pragma unroll
        for (int j = 0; j < CN; j++) {
            ull bp = packf2(bv[j], bv[j]);
#pragma unroll
            for (int p = 0; p < PAIRS; p++) fma2(acc[p][j], ap[p], bp);
        }
    }
}

#define STS_A(BUF, AV) \
    do { As[BUF][lk + 0][lrA] = (AV).x; As[BUF][lk + 1][lrA] = (AV).y; \
         As[BUF][lk + 2][lrA] = (AV).z; As[BUF][lk + 3][lrA] = (AV).w; } while (0)
#define STS_B(BUF, WV) \
    do { Bs[BUF][lk + 0][lrB] = (WV).x; Bs[BUF][lk + 1][lrB] = (WV).y; \
         Bs[BUF][lk + 2][lrB] = (WV).z; Bs[BUF][lk + 3][lrB] = (WV).w; } while (0)

// ---------------- LayerNorm ----------------
__global__ void k_layernorm(const float* __restrict__ x, const float* __restrict__ g,
                            const float* __restrict__ b) {
    int row = blockIdx.x, tid = threadIdx.x;
    float v = x[row * Dd + tid];
    float s = v, s2 = v * v;
#pragma unroll
    for (int o = 16; o; o >>= 1) {
        s += __shfl_xor_sync(0xffffffffu, s, o);
        s2 += __shfl_xor_sync(0xffffffffu, s2, o);
    }
    __shared__ float sh[8], sh2[8];
    int w = tid >> 5, l = tid & 31;
    if (l == 0) { sh[w] = s; sh2[w] = s2; }
    __syncthreads();
    if (tid == 0) {
        float a = 0, a2 = 0;
#pragma unroll
        for (int i = 0; i < 8; i++) { a += sh[i]; a2 += sh2[i]; }
        sh[0] = a; sh2[0] = a2;
    }
    __syncthreads();
    float mu = sh[0] * (1.f / Dd);
    float var = sh2[0] * (1.f / Dd) - mu * mu;
    float r = rsqrtf(var + 1e-5f);
    g_xnorm[row * Dd + tid] = (v - mu) * r * g[tid] + b[tid];
}

// ---------------- conv_w transpose: (O,I,4) -> (4,O,I) ----------------
__global__ void k_convwt(const float* __restrict__ cw) {
    int idx = blockIdx.x * 256 + threadIdx.x;
    float4 w = *(const float4*)(cw + (size_t)idx * 4);
    g_convwt[0 * 262144 + idx] = w.x;
    g_convwt[1 * 262144 + idx] = w.y;
    g_convwt[2 * 262144 + idx] = w.z;
    g_convwt[3 * 262144 + idx] = w.w;
}

// ---------------- generic TN GEMM, templated tile + epilogue -----------------
// EPI 0: C = acc + bias[n]           EPI 1: C = sigmoid(acc + bias[n])
// EPI 2: groupnorm/skip epilogue     EPI 3: C = acc + bias[n] + extra[m*N+n]
template <int BMt, int BNt, int EPI>
__global__ __launch_bounds__(256) void gemm_t(const float* __restrict__ A,
                                              const float* __restrict__ W,
                                              const float* __restrict__ bias,
                                              const float* __restrict__ extra,
                                              float* __restrict__ C,
                                              const float* __restrict__ W2,
                                              const float* __restrict__ bias2,
                                              float* __restrict__ C2,
                                              int N, int K) {
    if (W2 && blockIdx.z == 1) { W = W2; bias = bias2; C = C2; }
    constexpr int PAIRS = BMt / 32, CN = BNt / 16;
    __shared__ __align__(16) float As[2][BK][BMt + 4];
    __shared__ __align__(16) float Bs[2][BK][BNt + 4];
    int tid = threadIdx.x;
    int m0 = blockIdx.y * BMt, n0 = blockIdx.x * BNt;
    int ty = tid >> 4, tx = tid & 15;
    bool doA = (BMt == 64) || (tid < 128);
    bool doB = (BNt == 64) || (tid >= 128);
    int lrA = tid >> 2;
    int lrB = (BNt == 64) ? (tid >> 2) : ((tid & 127) >> 2);
    int lk = (tid & 3) * 4;
    const float* Ap = A + (size_t)(m0 + lrA) * K + lk;
    const float* Wp = W + (size_t)(n0 + lrB) * K + lk;
    ull acc[PAIRS][CN] = {};
    float4 a, w;
    if (doA) a = *(const float4*)Ap;
    if (doB) w = *(const float4*)Wp;
    if (doA) STS_A(0, a);
    if (doB) STS_B(0, w);
    __syncthreads();
    int buf = 0;
    for (int k0 = BK; k0 < K; k0 += BK) {
        if (doA) a = *(const float4*)(Ap + k0);
        if (doB) w = *(const float4*)(Wp + k0);
        mma_t<BMt, BNt>(As[buf], Bs[buf], ty, tx, acc);
        if (doA) STS_A(buf ^ 1, a);
        if (doB) STS_B(buf ^ 1, w);
        __syncthreads();
        buf ^= 1;
    }
    mma_t<BMt, BNt>(As[buf], Bs[buf], ty, tx, acc);

#pragma unroll
    for (int p = 0; p < PAIRS; p++) {
        float2 lohi[CN];
#pragma unroll
        for (int j = 0; j < CN; j++) lohi[j] = unpackf2(acc[p][j]);
#pragma unroll
        for (int half = 0; half < 2; half++) {
            int m = m0 + ty * (2 * PAIRS) + 2 * p + half;
            int n = n0 + tx * CN;
            float vv[CN], ov[CN];
#pragma unroll
            for (int j = 0; j < CN; j++) vv[j] = half ? lohi[j].y : lohi[j].x;
            if constexpr (EPI == 0) {
#pragma unroll
                for (int j = 0; j < CN; j++) ov[j] = vv[j] + bias[n + j];
            } else if constexpr (EPI == 1) {
#pragma unroll
                for (int j = 0; j < CN; j++) ov[j] = sigm(vv[j] + bias[n + j]);
            } else if constexpr (EPI == 2) {
                int b = m >> 8;
#pragma unroll
                for (int j = 0; j < CN; j++) {
                    int nn = n + j, hh = nn >> 7;
                    float mu = g_gnmu[b * 4 + hh], rs = g_gnrs[b * 4 + hh];
                    float zn = (g_hseq[(size_t)m * D2 + nn] - mu) * rs;
                    float hg = zn * bias[nn] + extra[nn] + vv[j];
                    float xr = g_xright[(size_t)m * D2 + nn];
                    ov[j] = hg * xr * sigm(xr);
                }
            } else {
#pragma unroll
                for (int j = 0; j < CN; j++)
                    ov[j] = vv[j] + bias[n + j] + extra[(size_t)m * N + n + j];
            }
            if constexpr (CN == 4)
                *(float4*)&C[(size_t)m * N + n] = make_float4(ov[0], ov[1], ov[2], ov[3]);
            else
                *(float2*)&C[(size_t)m * N + n] = make_float2(ov[0], ov[1]);
        }
    }
}

// ---------------- conv partial: one tap (tau) = K=512 GEMM -------------------
__global__ __launch_bounds__(256) void k_convp() {
    constexpr int BMt = 64, BNt = 64;
    __shared__ __align__(16) float As[2][BK][BMt + 4];
    __shared__ __align__(16) float Bs[2][BK][BNt + 4];
    int tid = threadIdx.x;
    int tau = blockIdx.z;
    int m0 = blockIdx.y * BMt, n0 = blockIdx.x * BNt;
    int ty = tid >> 4, tx = tid & 15;
    int lrA = tid >> 2, lrB = tid >> 2, lk = (tid & 3) * 4;
    int row = m0 + lrA, b = row >> 8, t = row & 255;
    int tp = t - 3 + tau;
    bool valid = (tp >= 0);
    const float* Ap = g_xleft + (size_t)(b * Tt + (valid ? tp : 0)) * D2 + lk;
    const float* Wp = g_convwt + (size_t)tau * 262144 + (size_t)(n0 + lrB) * D2 + lk;
    ull acc[2][4] = {};
    float4 zero4 = make_float4(0.f, 0.f, 0.f, 0.f);
    float4 a = valid ? *(const float4*)Ap : zero4;
    float4 w = *(const float4*)Wp;
    STS_A(0, a);
    STS_B(0, w);
    __syncthreads();
    int buf = 0;
    for (int k0 = BK; k0 < D2; k0 += BK) {
        a = valid ? *(const float4*)(Ap + k0) : zero4;
        w = *(const float4*)(Wp + k0);
        mma_t<64, 64>(As[buf], Bs[buf], ty, tx, acc);
        STS_A(buf ^ 1, a);
        STS_B(buf ^ 1, w);
        __syncthreads();
        buf ^= 1;
    }
    mma_t<64, 64>(As[buf], Bs[buf], ty, tx, acc);

    float* out = g_convp + (size_t)tau * (BT * D2);
#pragma unroll
    for (int p = 0; p < 2; p++) {
        float2 lohi[4];
#pragma unroll
        for (int j = 0; j < 4; j++) lohi[j] = unpackf2(acc[p][j]);
#pragma unroll
        for (int half = 0; half < 2; half++) {
            int m = m0 + ty * 4 + 2 * p + half;
            int n = n0 + tx * 4;
            float4 ov = make_float4(half ? lohi[0].y : lohi[0].x, half ? lohi[1].y : lohi[1].x,
                                    half ? lohi[2].y : lohi[2].x, half ? lohi[3].y : lohi[3].x);
            *(float4*)&out[(size_t)m * D2 + n] = ov;
        }
    }
}

// ---------------- conv epilogue: sum 4 partials + bias + swish ---------------
__global__ void k_convepi(const float* __restrict__ cb) {
    int idx = blockIdx.x * 256 + threadIdx.x;  // float4 index, 131072 total
    size_t off = (size_t)idx * 4;
    float4 s0 = *(const float4*)(g_convp + off);
    float4 s1 = *(const float4*)(g_convp + 524288 + off);
    float4 s2 = *(const float4*)(g_convp + 1048576 + off);
    float4 s3 = *(const float4*)(g_convp + 1572864 + off);
    int n = (idx & 127) * 4;
    float4 b4 = *(const float4*)&cb[n];
    float z0 = s0.x + s1.x + s2.x + s3.x + b4.x;
    float z1 = s0.y + s1.y + s2.y + s3.y + b4.y;
    float z2 = s0.z + s1.z + s2.z + s3.z + b4.z;
    float z3 = s0.w + s1.w + s2.w + s3.w + b4.w;
    *(float4*)(g_xtrans + off) = make_float4(z0 * sigm(z0), z1 * sigm(z1),
                                             z2 * sigm(z2), z3 * sigm(z3));
}

// ---------------- block-diagonal q/k/v projections (32x64 tiles) -------------
__global__ __launch_bounds__(256) void k_qkv(const float* __restrict__ Wq,
                                             const float* __restrict__ Wk,
                                             const float* __restrict__ Wv) {
    constexpr int BMt = 32, BNt = 64;
    __shared__ __align__(16) float As[2][BK][BMt + 4];
    __shared__ __align__(16) float Bs[2][BK][BNt + 4];
    int tid = threadIdx.x;
    int z = blockIdx.z, which = z >> 2, h = z & 3;
    const float* src = (which == 2) ? g_xleft : g_xtrans;
    const float* W = (which == 0) ? Wq : ((which == 1) ? Wk : Wv);
    float* dst = (which == 0) ? g_q : ((which == 1) ? g_k : g_v);
    float sc = (which == 1) ? SCALEF : 1.f;
    int m0 = blockIdx.y * BMt, n0 = blockIdx.x * BNt;
    int ty = tid >> 4, tx = tid & 15;
    bool doA = (tid < 128);
    int lrA = tid >> 2, lrB = tid >> 2, lk = (tid & 3) * 4;
    const float* Ap = src + (size_t)(m0 + lrA) * D2 + h * 128 + lk;
    const float* Wp = W + (size_t)h * 16384 + (size_t)(n0 + lrB) * 128 + lk;
    ull acc[1][4] = {};
    float4 a, w;
    if (doA) a = *(const float4*)Ap;
    w = *(const float4*)Wp;
    if (doA) STS_A(0, a);
    STS_B(0, w);
    __syncthreads();
    int buf = 0;
    for (int k0 = BK; k0 < 128; k0 += BK) {
        if (doA) a = *(const float4*)(Ap + k0);
        w = *(const float4*)(Wp + k0);
        mma_t<32, 64>(As[buf], Bs[buf], ty, tx, acc);
        if (doA) STS_A(buf ^ 1, a);
        STS_B(buf ^ 1, w);
        __syncthreads();
        buf ^= 1;
    }
    mma_t<32, 64>(As[buf], Bs[buf], ty, tx, acc);

    float2 lohi[4];
#pragma unroll
    for (int j = 0; j < 4; j++) lohi[j] = unpackf2(acc[0][j]);
#pragma unroll
    for (int half = 0; half < 2; half++) {
        int m = m0 + ty * 2 + half;
        float4 ov = make_float4(sc * (half ? lohi[0].y : lohi[0].x),
                                sc * (half ? lohi[1].y : lohi[1].x),
                                sc * (half ? lohi[2].y : lohi[2].x),
                                sc * (half ? lohi[3].y : lohi[3].x));
        *(float4*)&dst[(size_t)m * D2 + h * 128 + n0 + tx * 4] = ov;
    }
}

// ---------------- i_bar / f_bar GEMV + zero rowsum ----------------
__global__ void k_ibfb(const float* __restrict__ Wi, const float* __restrict__ Wf,
                       const float* __restrict__ bi, const float* __restrict__ bf) {
    int row = blockIdx.x * 8 + (threadIdx.x >> 5);
    int l = threadIdx.x & 31;
    const float* xr = g_xleft + (size_t)row * D2;
    float si = 0, sf = 0;
#pragma unroll 4
    for (int j = l; j < D2; j += 32) {
        float v = xr[j];
        si += v * Wi[j];
        sf += v * Wf[j];
    }
#pragma unroll
    for (int o = 16; o; o >>= 1) {
        si += __shfl_xor_sync(0xffffffffu, si, o);
        sf += __shfl_xor_sync(0xffffffffu, sf, o);
    }
    if (l == 0) {
        g_ib[row] = si + bi[0];
        g_fb[row] = sf + bf[0];
        g_rowsum[row] = 0.f;
    }
}

// ---------------- scalar gate scan ----------------
__global__ void k_scan() {
    int b = threadIdx.x;
    if (b < Bq) {
        float m = 0.f, F = 0.f;
        for (int t = 0; t < Tt; t++) {
            float ib = g_ib[b * Tt + t], fb = g_fb[b * Tt + t];
            float mn = fmaxf(fb + m, ib);
            F += fb;
            g_alpha[b * Tt + t] = ib - F;
            g_beta[b * Tt + t] = F - mn;
            m = mn;
        }
    }
}

// ---------------- attn scores, 32x32 tiles, above-diag tiles skipped --------
__global__ __launch_bounds__(256) void k_attn1() {
    constexpr int BMt = 32, BNt = 32;
    int m0 = blockIdx.y * BMt, n0 = blockIdx.x * BNt;
    if (n0 > m0) return;  // strictly above diagonal: never read downstream
    __shared__ __align__(16) float As[2][BK][BMt + 4];
    __shared__ __align__(16) float Bs[2][BK][BNt + 4];
    int tid = threadIdx.x;
    int z = blockIdx.z;
    int ty = tid >> 4, tx = tid & 15;
    bool doA = (tid < 128), doB = (tid >= 128);
    int lrA = tid >> 2, lrB = (tid & 127) >> 2, lk = (tid & 3) * 4;
    const float* Ap = g_q + (size_t)(z * Tt + m0 + lrA) * D2 + lk;
    const float* Wp = g_k + (size_t)(z * Tt + n0 + lrB) * D2 + lk;
    ull acc[1][2] = {};
    float4 a, w;
    if (doA) a = *(const float4*)Ap;
    if (doB) w = *(const float4*)Wp;
    if (doA) STS_A(0, a);
    if (doB) STS_B(0, w);
    __syncthreads();
    int buf = 0;
    for (int k0 = BK; k0 < D2; k0 += BK) {
        if (doA) a = *(const float4*)(Ap + k0);
        if (doB) w = *(const float4*)(Wp + k0);
        mma_t<32, 32>(As[buf], Bs[buf], ty, tx, acc);
        if (doA) STS_A(buf ^ 1, a);
        if (doB) STS_B(buf ^ 1, w);
        __syncthreads();
        buf ^= 1;
    }
    mma_t<32, 32>(As[buf], Bs[buf], ty, tx, acc);

    float2 lohi0 = unpackf2(acc[0][0]), lohi1 = unpackf2(acc[0][1]);
    float al0 = g_alpha[z * Tt + n0 + tx * 2];
    float al1 = g_alpha[z * Tt + n0 + tx * 2 + 1];
#pragma unroll
    for (int half = 0; half < 2; half++) {
        int t = m0 + ty * 2 + half;
        float be = g_beta[z * Tt + t];
        int s0 = n0 + tx * 2, s1 = s0 + 1;
        float v0 = (s0 <= t) ? __expf(al0 + be) * (half ? lohi0.y : lohi0.x) : 0.f;
        float v1 = (s1 <= t) ? __expf(al1 + be) * (half ? lohi1.y : lohi1.x) : 0.f;
        *(float2*)&g_A[(size_t)z * Tt * Tt + (size_t)t * Tt + s0] = make_float2(v0, v1);
        float p = v0 + v1;
#pragma unroll
        for (int off = 1; off < 16; off <<= 1) p += __shfl_xor_sync(0xffffffffu, p, off);
        if (tx == 0) atomicAdd(&g_rowsum[z * Tt + t], p);
    }
}

// ---------------- h = (A @ V)/denom * o; K truncated to causal bound --------
__global__ __launch_bounds__(256) void k_attn2() {
    constexpr int BMt = 32, BNt = 64;
    __shared__ __align__(16) float As[2][BK][BMt + 4];
    __shared__ __align__(16) float Bs[2][BK][BNt + 4];
    int tid = threadIdx.x;
    int z = blockIdx.z;
    int m0 = blockIdx.y * BMt, n0 = blockIdx.x * BNt;
    int ty = tid >> 4, tx = tid & 15;
    bool doA = (tid < 128);
    int lrA = tid >> 2, lk = (tid & 3) * 4;
    int brow = tid >> 4, bcol = (tid & 15) * 4;
    int Kend = m0 + BMt;  // A cols beyond m0+31 are zero for these rows
    const float* Ap = g_A + (size_t)z * Tt * Tt + (size_t)(m0 + lrA) * Tt + lk;
    const float* Vb = g_v + (size_t)z * Tt * D2;
    ull acc[1][4] = {};
    float4 a, w;
    if (doA) a = *(const float4*)Ap;
    w = *(const float4*)(Vb + (size_t)brow * D2 + n0 + bcol);
    if (doA) STS_A(0, a);
    *(float4*)&Bs[0][brow][bcol] = w;
    __syncthreads();
    int buf = 0;
    for (int k0 = BK; k0 < Kend; k0 += BK) {
        if (doA) a = *(const float4*)(Ap + k0);
        w = *(const float4*)(Vb + (size_t)(k0 + brow) * D2 + n0 + bcol);
        mma_t<32, 64>(As[buf], Bs[buf], ty, tx, acc);
        if (doA) STS_A(buf ^ 1, a);
        *(float4*)&Bs[buf ^ 1][brow][bcol] = w;
        __syncthreads();
        buf ^= 1;
    }
    mma_t<32, 64>(As[buf], Bs[buf], ty, tx, acc);

    float2 lohi[4];
#pragma unroll
    for (int j = 0; j < 4; j++) lohi[j] = unpackf2(acc[0][j]);
#pragma unroll
    for (int half = 0; half < 2; half++) {
        int m = m0 + ty * 2 + half;
        int r = z * Tt + m;
        float rs = g_rowsum[r];
        float inv = 1.f / (fmaxf(fabsf(rs), 1.f) + 1e-8f);
        float4 og = *(const float4*)&g_o[(size_t)r * D2 + n0 + tx * 4];
        float4 ov = make_float4((half ? lohi[0].y : lohi[0].x) * inv * og.x,
                                (half ? lohi[1].y : lohi[1].x) * inv * og.y,
                                (half ? lohi[2].y : lohi[2].x) * inv * og.z,
                                (half ? lohi[3].y : lohi[3].x) * inv * og.w);
        *(float4*)&g_hseq[(size_t)r * D2 + n0 + tx * 4] = ov;
    }
}

// ---------------- GroupNorm stats over (T, DH) per (b, h) ----------------
__global__ void k_gnstats() {
    int bh = blockIdx.x;
    int b = bh >> 2, h = bh & 3;
    int tid = threadIdx.x;
    float s = 0, s2 = 0;
    const float* base = g_hseq + (size_t)(b * Tt) * D2 + h * 128;
    for (int i = tid; i < Tt * 128; i += 256) {
        int t = i >> 7, d = i & 127;
        float v = base[(size_t)t * D2 + d];
        s += v; s2 += v * v;
    }
#pragma unroll
    for (int o = 16; o; o >>= 1) {
        s += __shfl_xor_sync(0xffffffffu, s, o);
        s2 += __shfl_xor_sync(0xffffffffu, s2, o);
    }
    __shared__ float sh[8], sh2[8];
    int w = tid >> 5, l = tid & 31;
    if (l == 0) { sh[w] = s; sh2[w] = s2; }
    __syncthreads();
    if (tid == 0) {
        float a = 0, a2 = 0;
#pragma unroll
        for (int i = 0; i < 8; i++) { a += sh[i]; a2 += sh2[i]; }
        float mu = a * (1.f / (Tt * 128));
        float var = a2 * (1.f / (Tt * 128)) - mu * mu;
        g_gnmu[bh] = mu;
        g_gnrs[bh] = rsqrtf(var + 1e-5f);
    }
}

// ---------------- launch ----------------
extern "C" void kernel_launch(void* const* d_in, const int* in_sizes, int n_in,
                              void* d_out, int out_size) {
    const float* x       = (const float*)d_in[0];
    const float* ln_g    = (const float*)d_in[1];
    const float* ln_b    = (const float*)d_in[2];
    const float* W_left  = (const float*)d_in[3];
    const float* b_left  = (const float*)d_in[4];
    const float* W_right = (const float*)d_in[5];
    const float* b_right = (const float*)d_in[6];
    const float* Wi      = (const float*)d_in[7];
    const float* bi      = (const float*)d_in[8];
    const float* Wf      = (const float*)d_in[9];
    const float* bf      = (const float*)d_in[10];
    const float* Wo      = (const float*)d_in[11];
    const float* bo      = (const float*)d_in[12];
    const float* Wq      = (const float*)d_in[13];
    const float* Wk      = (const float*)d_in[14];
    const float* Wv      = (const float*)d_in[15];
    const float* conv_w  = (const float*)d_in[16];
    const float* conv_b  = (const float*)d_in[17];
    const float* skip_W  = (const float*)d_in[18];
    const float* gn_g    = (const float*)d_in[19];
    const float* gn_b    = (const float*)d_in[20];
    const float* W_last  = (const float*)d_in[21];
    const float* b_last  = (const float*)d_in[22];
    float* out = (float*)d_out;

    float *p_xnorm, *p_xleft, *p_xright, *p_xtrans, *p_o, *p_h;
    cudaGetSymbolAddress((void**)&p_xnorm, g_xnorm);
    cudaGetSymbolAddress((void**)&p_xleft, g_xleft);
    cudaGetSymbolAddress((void**)&p_xright, g_xright);
    cudaGetSymbolAddress((void**)&p_xtrans, g_xtrans);
    cudaGetSymbolAddress((void**)&p_o, g_o);
    cudaGetSymbolAddress((void**)&p_h, g_h);

    k_layernorm<<<BT, 256>>>(x, ln_g, ln_b);
    k_convwt<<<1024, 256>>>(conv_w);
    // fused left+right projections: 512 CTAs
    gemm_t<32, 64, 0><<<dim3(8, 32, 2), 256>>>(p_xnorm, W_left, b_left, nullptr, p_xleft,
                                               W_right, b_right, p_xright, 512, 256);
    k_convp<<<dim3(8, 16, 4), 256>>>();
    k_convepi<<<512, 256>>>(conv_b);
    gemm_t<32, 64, 1><<<dim3(8, 32, 1), 256>>>(p_xleft, Wo, bo, nullptr, p_o,
                                               nullptr, nullptr, nullptr, 512, 512);
    k_ibfb<<<128, 256>>>(Wi, Wf, bi, bf);
    k_scan<<<1, 32>>>();
    k_qkv<<<dim3(2, 32, 12), 256>>>(Wq, Wk, Wv);
    k_attn1<<<dim3(8, 8, 4), 256>>>();
    k_attn2<<<dim3(8, 8, 4), 256>>>();
    k_gnstats<<<16, 256>>>();
    gemm_t<32, 64, 2><<<dim3(8, 32, 1), 256>>>(p_xtrans, skip_W, gn_g, gn_b, p_h,
                                               nullptr, nullptr, nullptr, 512, 512);
    gemm_t<32, 32, 3><<<dim3(8, 32, 1), 256>>>(p_h, W_last, b_last, x, out,
                                               nullptr, nullptr, nullptr, 256, 512);
}